// round 2
// baseline (speedup 1.0000x reference)
#include <cuda_runtime.h>
#include <math.h>

// Problem dims (fixed by reference)
#define BB 4
#define SS 2048
#define EE 1024
#define DD 1024

// Scratch (device globals — no allocation allowed in kernel_launch)
__device__ __align__(16) float g_q[(size_t)BB * SS * DD];
__device__ __align__(16) float g_k[(size_t)BB * SS * DD];
__device__ __align__(16) float g_v[(size_t)BB * SS * DD];
__device__ __align__(16) float g_s[(size_t)BB * SS * SS];   // scores, TRANSPOSED: sT[b][k][q]

// ---------------------------------------------------------------------------
// Tiled SGEMM. 128x128 block tile, K-tile 8, 256 threads, 8x8 per-thread.
// MODE 0: C = A(row-major MxK) @ B(row-major KxN) + bias[N]           (proj)
// MODE 1: C[m,n] = scale * sum_d A[m,d]*B[n,d]   (A: MxK, B: NxK)     (k @ q^T)
// MODE 2: C[m,n] = sum_k A[k,m]*B[k,n]           (A: KxM, B: KxN)     (attnT^T @ V)
// All dims assumed multiples of tile sizes (true for this problem).
// ---------------------------------------------------------------------------
#define BM 128
#define BN 128
#define BK 8
#define TM 8
#define TN 8

template <int MODE>
__global__ __launch_bounds__(256, 2)
void gemm_kernel(const float* __restrict__ A, const float* __restrict__ Bm,
                 const float* __restrict__ bias, float* __restrict__ C,
                 int M, int N, int K, float scale,
                 size_t strideA, size_t strideB, size_t strideC)
{
    const int bz = blockIdx.z;
    A  += (size_t)bz * strideA;
    Bm += (size_t)bz * strideB;
    C  += (size_t)bz * strideC;

    __shared__ float As[BK][BM + 4];
    __shared__ float Bs[BK][BN + 4];

    const int t  = threadIdx.x;
    const int tx = t & 15;        // 0..15
    const int ty = t >> 4;        // 0..15
    const int m0 = blockIdx.y * BM;
    const int n0 = blockIdx.x * BN;

    float acc[TM][TN];
#pragma unroll
    for (int i = 0; i < TM; i++)
#pragma unroll
        for (int j = 0; j < TN; j++) acc[i][j] = 0.f;

    for (int k0 = 0; k0 < K; k0 += BK) {
        // ---- load A tile into As[kk][m] ----
        if (MODE == 0 || MODE == 1) {
            // A row-major [M, K]: tile BM x BK, one float4 along K per thread
            const int m  = t >> 1;            // 0..127
            const int kq = (t & 1) * 4;       // 0 or 4
            float4 av = *reinterpret_cast<const float4*>(
                &A[(size_t)(m0 + m) * K + k0 + kq]);
            As[kq + 0][m] = av.x; As[kq + 1][m] = av.y;
            As[kq + 2][m] = av.z; As[kq + 3][m] = av.w;
        } else {
            // A row-major [K, M]: tile BK x BM, one float4 along M per thread
            const int kk = t >> 5;            // 0..7
            const int m4 = (t & 31) * 4;      // 0..124
            float4 av = *reinterpret_cast<const float4*>(
                &A[(size_t)(k0 + kk) * M + m0 + m4]);
            As[kk][m4 + 0] = av.x; As[kk][m4 + 1] = av.y;
            As[kk][m4 + 2] = av.z; As[kk][m4 + 3] = av.w;
        }
        // ---- load B tile into Bs[kk][n] ----
        if (MODE == 0 || MODE == 2) {
            // B row-major [K, N]
            const int kk = t >> 5;
            const int n4 = (t & 31) * 4;
            float4 bv = *reinterpret_cast<const float4*>(
                &Bm[(size_t)(k0 + kk) * N + n0 + n4]);
            Bs[kk][n4 + 0] = bv.x; Bs[kk][n4 + 1] = bv.y;
            Bs[kk][n4 + 2] = bv.z; Bs[kk][n4 + 3] = bv.w;
        } else {
            // MODE 1: B row-major [N, K]
            const int n  = t >> 1;
            const int kq = (t & 1) * 4;
            float4 bv = *reinterpret_cast<const float4*>(
                &Bm[(size_t)(n0 + n) * K + k0 + kq]);
            Bs[kq + 0][n] = bv.x; Bs[kq + 1][n] = bv.y;
            Bs[kq + 2][n] = bv.z; Bs[kq + 3][n] = bv.w;
        }
        __syncthreads();

#pragma unroll
        for (int kk = 0; kk < BK; kk++) {
            float a[TM], b[TN];
#pragma unroll
            for (int i = 0; i < TM; i++) a[i] = As[kk][i * 16 + ty];
#pragma unroll
            for (int j = 0; j < TN; j++) b[j] = Bs[kk][j * 16 + tx];
#pragma unroll
            for (int i = 0; i < TM; i++)
#pragma unroll
                for (int j = 0; j < TN; j++)
                    acc[i][j] += a[i] * b[j];
        }
        __syncthreads();
    }

    // ---- epilogue ----
#pragma unroll
    for (int i = 0; i < TM; i++) {
        const int m = m0 + i * 16 + ty;
#pragma unroll
        for (int j = 0; j < TN; j++) {
            const int n = n0 + j * 16 + tx;
            float v = acc[i][j] * scale;
            if (MODE == 0) v += bias[n];
            C[(size_t)m * N + n] = v;
        }
    }
}

// ---------------------------------------------------------------------------
// Row softmax over contiguous rows of length SS (=2048). One block per row,
// 256 threads, 8 elements each.
// ---------------------------------------------------------------------------
__global__ __launch_bounds__(256)
void softmax_rows_kernel(float* __restrict__ s)
{
    float* row = s + (size_t)blockIdx.x * SS;
    const int t = threadIdx.x;

    float vals[8];
    float m = -INFINITY;
#pragma unroll
    for (int i = 0; i < 8; i++) {
        vals[i] = row[t + i * 256];
        m = fmaxf(m, vals[i]);
    }
    __shared__ float red[8];
#pragma unroll
    for (int o = 16; o > 0; o >>= 1) m = fmaxf(m, __shfl_xor_sync(0xFFFFFFFFu, m, o));
    if ((t & 31) == 0) red[t >> 5] = m;
    __syncthreads();
    m = red[0];
#pragma unroll
    for (int i = 1; i < 8; i++) m = fmaxf(m, red[i]);
    __syncthreads();

    float sum = 0.f;
#pragma unroll
    for (int i = 0; i < 8; i++) {
        vals[i] = __expf(vals[i] - m);
        sum += vals[i];
    }
#pragma unroll
    for (int o = 16; o > 0; o >>= 1) sum += __shfl_xor_sync(0xFFFFFFFFu, sum, o);
    if ((t & 31) == 0) red[t >> 5] = sum;
    __syncthreads();
    sum = red[0];
#pragma unroll
    for (int i = 1; i < 8; i++) sum += red[i];
    const float rinv = 1.0f / sum;
#pragma unroll
    for (int i = 0; i < 8; i++) row[t + i * 256] = vals[i] * rinv;
}

// ---------------------------------------------------------------------------
extern "C" void kernel_launch(void* const* d_in, const int* in_sizes, int n_in,
                              void* d_out, int out_size)
{
    const float* x  = (const float*)d_in[0];
    const float* Wq = (const float*)d_in[1];
    const float* bq = (const float*)d_in[2];
    const float* Wk = (const float*)d_in[3];
    const float* bk = (const float*)d_in[4];
    const float* Wv = (const float*)d_in[5];
    const float* bv = (const float*)d_in[6];
    float* out = (float*)d_out;

    float *q, *k, *v, *s;
    cudaGetSymbolAddress((void**)&q, g_q);
    cudaGetSymbolAddress((void**)&k, g_k);
    cudaGetSymbolAddress((void**)&v, g_v);
    cudaGetSymbolAddress((void**)&s, g_s);

    const dim3 thr(256);

    // 1) QKV projections: [B*S, E] @ [E, D] + bias   (MODE 0)
    {
        dim3 grid(DD / BN, (BB * SS) / BM, 1);
        gemm_kernel<0><<<grid, thr>>>(x, Wq, bq, q, BB * SS, DD, EE, 1.0f, 0, 0, 0);
        gemm_kernel<0><<<grid, thr>>>(x, Wk, bk, k, BB * SS, DD, EE, 1.0f, 0, 0, 0);
        gemm_kernel<0><<<grid, thr>>>(x, Wv, bv, v, BB * SS, DD, EE, 1.0f, 0, 0, 0);
    }

    // 2) Transposed scores: sT[b][krow][qcol] = (1/sqrt(D)) * sum_d k[b,krow,d]*q[b,qcol,d]
    //    MODE 1 (NT), batched over z.
    {
        dim3 grid(SS / BN, SS / BM, BB);
        gemm_kernel<1><<<grid, thr>>>(k, q, nullptr, s, SS, SS, DD,
                                      1.0f / 32.0f,   // 1/sqrt(1024)
                                      (size_t)SS * DD, (size_t)SS * DD,
                                      (size_t)SS * SS);
    }

    // 3) Softmax over the query axis == contiguous row softmax on sT
    softmax_rows_kernel<<<BB * SS, thr>>>(s);

    // 4) out[b,q,v] = sum_k attnT[b,k,q] * v[b,k,v]   (MODE 2, TN), batched.
    {
        dim3 grid(DD / BN, SS / BM, BB);
        gemm_kernel<2><<<grid, thr>>>(s, v, nullptr, out, SS, DD, SS, 1.0f,
                                      (size_t)SS * SS, (size_t)SS * DD,
                                      (size_t)SS * DD);
    }
}

// round 5
// speedup vs baseline: 2.3589x; 2.3589x over previous
#include <cuda_runtime.h>
#include <cstdint>
#include <math.h>

#define BB 4
#define SS 2048
#define EE 1024
#define DD 1024

// ------------------------- scratch (device globals) -------------------------
__device__ __align__(256) float g_q [(size_t)BB * SS * DD];
__device__ __align__(256) float g_k [(size_t)BB * SS * DD];
__device__ __align__(256) float g_vT[(size_t)DD * BB * SS];   // [dv][b*S+s]
__device__ __align__(256) float g_s [(size_t)BB * SS * SS];   // scores [b][q][k]
__device__ __align__(256) float g_wT[3][(size_t)DD * EE];     // WqT, WkT, WvT

// ------------------------- helpers ------------------------------------------
__device__ __forceinline__ uint32_t smem_to_u32(const void* p) {
    uint32_t a;
    asm("{ .reg .u64 t; cvta.to.shared.u64 t, %1; cvt.u32.u64 %0, t; }"
        : "=r"(a) : "l"(p));
    return a;
}
__device__ __forceinline__ float to_tf32(float x) {
    float y;
    asm("cvt.rna.tf32.f32 %0, %1;" : "=f"(y) : "f"(x));
    return y;
}
__device__ __forceinline__ uint32_t swz(uint32_t off) {
    return off ^ ((off >> 3) & 0x70);   // Swizzle<3,4,3>: bits[4:6] ^= bits[7:9]
}

#define LDSM_X4(r, addr) \
    asm volatile("ldmatrix.sync.aligned.m8n8.x4.shared.b16 {%0,%1,%2,%3}, [%4];" \
        : "=r"((r)[0]), "=r"((r)[1]), "=r"((r)[2]), "=r"((r)[3]) : "r"(addr))

__device__ __forceinline__ void mma_tf32(float* d, uint32_t a0, uint32_t a1,
                                         uint32_t a2, uint32_t a3,
                                         uint32_t b0, uint32_t b1) {
    asm volatile(
        "mma.sync.aligned.m16n8k8.row.col.f32.tf32.tf32.f32 "
        "{%0,%1,%2,%3}, {%4,%5,%6,%7}, {%8,%9}, {%0,%1,%2,%3};"
        : "+f"(d[0]), "+f"(d[1]), "+f"(d[2]), "+f"(d[3])
        : "r"(a0), "r"(a1), "r"(a2), "r"(a3), "r"(b0), "r"(b1));
}

// ------------------------- mma.sync tf32 GEMM --------------------------------
// D[m][n] = scale * sum_k A[m][k] * B[n][k]  (+ bias[n] (mode1) or bias[m] (mode2))
// CTA tile 128x128, BK=32, 8 warps (2x4), warp tile 64x32.
// SMEM: A/B tiles 128x32 f32 (128B rows, swizzled), double-buffered.
#define GEMM_SMEM_BYTES (65536 + 1024)

__global__ __launch_bounds__(256)
void mma_gemm_tf32(const float* __restrict__ A, const float* __restrict__ B,
                   const float* __restrict__ bias, float* __restrict__ C,
                   int K, int ldA, int ldB, int ldC, float scale, int bias_mode,
                   size_t sA, size_t sB, size_t sC)
{
    extern __shared__ char dsm[];
    const uint32_t raw = smem_to_u32(dsm);
    const uint32_t sb = (raw + 1023u) & ~1023u;
    char* sm = dsm + (sb - raw);

    const int tid  = threadIdx.x;
    const int lane = tid & 31;
    const int wid  = tid >> 5;
    const int bz = blockIdx.z;
    A += (size_t)bz * sA;
    B += (size_t)bz * sB;
    C += (size_t)bz * sC;
    const int m0 = blockIdx.y * 128;
    const int n0 = blockIdx.x * 128;
    const int warp_m = (wid >> 2) * 64;   // 0 or 64
    const int warp_n = (wid & 3) * 32;    // 0,32,64,96

    // ldmatrix per-lane addressing: threads 0-7 -> M0, 8-15 -> M1, 16-23 -> M2, 24-31 -> M3
    // M0: rows r0-7, k 0-3 | M1: rows r0-7, k 4-7 | M2: rows r8-15, k 0-3 | M3: rows r8-15, k 4-7
    const int lrow  = (lane & 7) | ((lane & 16) >> 1);   // row within 16-row frag
    const int lcolb = ((lane >> 3) & 1) * 16;            // 0 or 16 bytes

    const uint32_t sA0 = sb;
    const uint32_t sB0 = sb + 16384;
    const uint32_t sA1 = sb + 32768;
    const uint32_t sB1 = sb + 49152;

    float acc[4][4][4];
#pragma unroll
    for (int i = 0; i < 4; i++)
#pragma unroll
        for (int j = 0; j < 4; j++)
#pragma unroll
            for (int r = 0; r < 4; r++) acc[i][j][r] = 0.f;

    // staging thread map: idx = i*256+tid; row = idx>>3 (0..127), colb = (idx&7)*16
    const int st_r  = tid >> 3;
    const int st_cb = (tid & 7) * 16;

    const int KT = K >> 5;
    float4 pA[4], pB[4];

    // ---- load tile kt into prefetch regs ----
    auto LDG_TILE = [&](int kt) {
        const float* Ag = A + kt * 32;
        const float* Bg = B + kt * 32;
#pragma unroll
        for (int i = 0; i < 4; i++) {
            const int r = st_r + i * 32;
            pA[i] = *reinterpret_cast<const float4*>(
                Ag + (size_t)(m0 + r) * ldA + (st_cb >> 2));
            pB[i] = *reinterpret_cast<const float4*>(
                Bg + (size_t)(n0 + r) * ldB + (st_cb >> 2));
        }
    };
    // ---- cvt + store prefetch regs into smem buffer ----
    auto STS_TILE = [&](uint32_t Ab, uint32_t Bb) {
#pragma unroll
        for (int i = 0; i < 4; i++) {
            const int r = st_r + i * 32;
            float4 v = pA[i];
            v.x = to_tf32(v.x); v.y = to_tf32(v.y);
            v.z = to_tf32(v.z); v.w = to_tf32(v.w);
            *reinterpret_cast<float4*>(sm + (Ab - sb) + swz(r * 128 + st_cb)) = v;
            float4 w = pB[i];
            w.x = to_tf32(w.x); w.y = to_tf32(w.y);
            w.z = to_tf32(w.z); w.w = to_tf32(w.w);
            *reinterpret_cast<float4*>(sm + (Bb - sb) + swz(r * 128 + st_cb)) = w;
        }
    };
    // ---- compute one 128x128x32 tile from smem ----
    auto COMPUTE = [&](uint32_t Ab, uint32_t Bb) {
#pragma unroll
        for (int ks = 0; ks < 4; ks++) {
            uint32_t a[4][4];
#pragma unroll
            for (int mf = 0; mf < 4; mf++) {
                uint32_t off = (uint32_t)((warp_m + mf * 16 + lrow) * 128
                                          + ks * 32 + lcolb);
                LDSM_X4(a[mf], Ab + swz(off));
            }
            uint32_t b[2][4];
#pragma unroll
            for (int g = 0; g < 2; g++) {
                uint32_t off = (uint32_t)((warp_n + g * 16 + lrow) * 128
                                          + ks * 32 + lcolb);
                LDSM_X4(b[g], Bb + swz(off));
            }
#pragma unroll
            for (int mf = 0; mf < 4; mf++)
#pragma unroll
                for (int nf = 0; nf < 4; nf++) {
                    const uint32_t* bp = &b[nf >> 1][(nf & 1) * 2];
                    // ldmatrix reg order (M0,M1,M2,M3) = (a0,a2,a1,a3)
                    mma_tf32(acc[mf][nf], a[mf][0], a[mf][2], a[mf][1], a[mf][3],
                             bp[0], bp[1]);
                }
        }
    };

    LDG_TILE(0);
    STS_TILE(sA0, sB0);
    __syncthreads();

    for (int kt = 0; kt < KT; kt++) {
        const bool more = (kt + 1) < KT;
        if (more) LDG_TILE(kt + 1);
        if (kt & 1) COMPUTE(sA1, sB1);
        else        COMPUTE(sA0, sB0);
        if (more) {
            if ((kt + 1) & 1) STS_TILE(sA1, sB1);
            else              STS_TILE(sA0, sB0);
            __syncthreads();
        }
    }

    // ---- epilogue: acc frag layout c0:(r, 2c) c1:(r, 2c+1) c2:(r+8, 2c) c3:(r+8, 2c+1)
#pragma unroll
    for (int mf = 0; mf < 4; mf++) {
        const int r = m0 + warp_m + mf * 16 + (lane >> 2);
#pragma unroll
        for (int nf = 0; nf < 4; nf++) {
            const int c = n0 + warp_n + nf * 8 + (lane & 3) * 2;
            float v0 = acc[mf][nf][0] * scale;
            float v1 = acc[mf][nf][1] * scale;
            float v2 = acc[mf][nf][2] * scale;
            float v3 = acc[mf][nf][3] * scale;
            if (bias_mode == 1) {
                const float b0 = bias[c], b1 = bias[c + 1];
                v0 += b0; v1 += b1; v2 += b0; v3 += b1;
            } else if (bias_mode == 2) {
                const float bm0 = bias[r], bm1 = bias[r + 8];
                v0 += bm0; v1 += bm0; v2 += bm1; v3 += bm1;
            }
            float2 lo = make_float2(v0, v1);
            float2 hi = make_float2(v2, v3);
            *reinterpret_cast<float2*>(&C[(size_t)r * ldC + c]) = lo;
            *reinterpret_cast<float2*>(&C[(size_t)(r + 8) * ldC + c]) = hi;
        }
    }
}

// ------------------------- column softmax (over q axis) ----------------------
__global__ __launch_bounds__(256)
void softmax_cols(float* __restrict__ sdat)
{
    const int kcol = blockIdx.x * 256 + threadIdx.x;
    float* p = sdat + (size_t)blockIdx.y * SS * SS + kcol;

    float m0 = -3e38f, m1 = -3e38f, m2 = -3e38f, m3 = -3e38f;
    for (int q = 0; q < SS; q += 4) {
        m0 = fmaxf(m0, p[(size_t)(q + 0) * SS]);
        m1 = fmaxf(m1, p[(size_t)(q + 1) * SS]);
        m2 = fmaxf(m2, p[(size_t)(q + 2) * SS]);
        m3 = fmaxf(m3, p[(size_t)(q + 3) * SS]);
    }
    const float m = fmaxf(fmaxf(m0, m1), fmaxf(m2, m3));

    float s0 = 0.f, s1 = 0.f, s2 = 0.f, s3 = 0.f;
    for (int q = 0; q < SS; q += 4) {
        s0 += __expf(p[(size_t)(q + 0) * SS] - m);
        s1 += __expf(p[(size_t)(q + 1) * SS] - m);
        s2 += __expf(p[(size_t)(q + 2) * SS] - m);
        s3 += __expf(p[(size_t)(q + 3) * SS] - m);
    }
    const float inv = 1.0f / (s0 + s1 + s2 + s3);

    for (int q = 0; q < SS; q += 4) {
#pragma unroll
        for (int j = 0; j < 4; j++) {
            float* a = p + (size_t)(q + j) * SS;
            *a = __expf(*a - m) * inv;
        }
    }
}

// ------------------------- tiled transpose -----------------------------------
__global__ __launch_bounds__(256)
void transpose_mat(const float* __restrict__ in, float* __restrict__ out,
                   int R, int C)
{
    __shared__ float t[32][33];
    const int x = blockIdx.x * 32 + threadIdx.x;
    const int y = blockIdx.y * 32 + threadIdx.y;
#pragma unroll
    for (int j = 0; j < 32; j += 8)
        t[threadIdx.y + j][threadIdx.x] = in[(size_t)(y + j) * C + x];
    __syncthreads();
    const int x2 = blockIdx.y * 32 + threadIdx.x;
    const int y2 = blockIdx.x * 32 + threadIdx.y;
#pragma unroll
    for (int j = 0; j < 32; j += 8)
        out[(size_t)(y2 + j) * R + x2] = t[threadIdx.x][threadIdx.y + j];
}

// -----------------------------------------------------------------------------
extern "C" void kernel_launch(void* const* d_in, const int* in_sizes, int n_in,
                              void* d_out, int out_size)
{
    const float* x  = (const float*)d_in[0];
    const float* Wq = (const float*)d_in[1];
    const float* bq = (const float*)d_in[2];
    const float* Wk = (const float*)d_in[3];
    const float* bk = (const float*)d_in[4];
    const float* Wv = (const float*)d_in[5];
    const float* bv = (const float*)d_in[6];
    float* out = (float*)d_out;

    float *q, *k, *vT, *s, *wT;
    cudaGetSymbolAddress((void**)&q,  g_q);
    cudaGetSymbolAddress((void**)&k,  g_k);
    cudaGetSymbolAddress((void**)&vT, g_vT);
    cudaGetSymbolAddress((void**)&s,  g_s);
    cudaGetSymbolAddress((void**)&wT, g_wT);
    float* WqT = wT;
    float* WkT = wT + (size_t)EE * DD;
    float* WvT = wT + 2 * (size_t)EE * DD;

    cudaFuncSetAttribute(mma_gemm_tf32,
                         cudaFuncAttributeMaxDynamicSharedMemorySize,
                         GEMM_SMEM_BYTES);

    // 0) transpose weights: W[E][D] -> WT[D][E]
    {
        dim3 thr(32, 8), grid(DD / 32, EE / 32);
        transpose_mat<<<grid, thr>>>(Wq, WqT, EE, DD);
        transpose_mat<<<grid, thr>>>(Wk, WkT, EE, DD);
        transpose_mat<<<grid, thr>>>(Wv, WvT, EE, DD);
    }

    const dim3 thr(256);

    // 1) q = x @ Wq + bq ; k likewise  (A = x [BS][E], B = WT [D][E])
    {
        dim3 grid(DD / 128, (BB * SS) / 128, 1);
        mma_gemm_tf32<<<grid, thr, GEMM_SMEM_BYTES>>>(
            x, WqT, bq, q, EE, EE, EE, DD, 1.0f, 1, 0, 0, 0);
        mma_gemm_tf32<<<grid, thr, GEMM_SMEM_BYTES>>>(
            x, WkT, bk, k, EE, EE, EE, DD, 1.0f, 1, 0, 0, 0);
    }
    // 2) vT = (x @ Wv + bv)^T  (A = WvT [Dv][E], B = x [BS][E], bias by row)
    {
        dim3 grid((BB * SS) / 128, DD / 128, 1);
        mma_gemm_tf32<<<grid, thr, GEMM_SMEM_BYTES>>>(
            WvT, x, bv, vT, EE, EE, EE, BB * SS, 1.0f, 2, 0, 0, 0);
    }
    // 3) scores s[b][q][k] = (1/32) q·k^T
    {
        dim3 grid(SS / 128, SS / 128, BB);
        mma_gemm_tf32<<<grid, thr, GEMM_SMEM_BYTES>>>(
            q, k, nullptr, s, DD, DD, DD, SS, 1.0f / 32.0f, 0,
            (size_t)SS * DD, (size_t)SS * DD, (size_t)SS * SS);
    }
    // 4) softmax over q axis (column softmax)
    {
        dim3 grid(SS / 256, BB);
        softmax_cols<<<grid, thr>>>(s);
    }
    // 5) out[b][q][dv] = attn[q][:] · vT[dv][:]  (A = s, B = vT cols shifted per batch)
    {
        dim3 grid(DD / 128, SS / 128, BB);
        mma_gemm_tf32<<<grid, thr, GEMM_SMEM_BYTES>>>(
            s, vT, nullptr, out, SS, SS, BB * SS, DD, 1.0f, 0,
            (size_t)SS * SS, (size_t)SS, (size_t)SS * DD);
    }
}